// round 2
// baseline (speedup 1.0000x reference)
#include <cuda_runtime.h>
#include <math.h>

#define B_  32
#define S_  2048
#define D_  1024
#define BN_ 64
#define E_  8

// ---------------- scratch (device globals; no allocation) ----------------
__device__ float g_partial[B_][16][E_];          // per-(b,chunk) partial gate sums
__device__ int   g_eidx[B_][2];
__device__ float g_ew[B_][2];
__device__ float g_bvec[B_][D_];                 // combined up-bias per batch
__device__ float g_h[(size_t)B_ * 2 * S_ * BN_]; // (b, k, s, c) gelu'd+weighted hidden (32 MB)

// ---------------- helpers ----------------
__device__ __forceinline__ unsigned f2tf(float f) {
    unsigned u; asm("cvt.rna.tf32.f32 %0, %1;" : "=r"(u) : "f"(f)); return u;
}
__device__ __forceinline__ float gelu_exact(float v) {
    return 0.5f * v * (1.0f + erff(v * 0.7071067811865476f));
}

#define MMA_TF32(d, a, bb) asm volatile( \
    "mma.sync.aligned.m16n8k8.row.col.f32.tf32.tf32.f32 " \
    "{%0,%1,%2,%3},{%4,%5,%6,%7},{%8,%9},{%0,%1,%2,%3};" \
    : "+f"(d[0]), "+f"(d[1]), "+f"(d[2]), "+f"(d[3]) \
    : "r"(a[0]), "r"(a[1]), "r"(a[2]), "r"(a[3]), "r"(bb[0]), "r"(bb[1]))

// ---------------- kernel 1: gate logit partials (streams x once) ----------------
// grid (16, 32), 256 threads. Thread t owns d in [4t, 4t+4); gate_w slice in registers.
__global__ void __launch_bounds__(256) k_gate_partial(const float* __restrict__ x,
                                                      const float* __restrict__ gate_w) {
    int b = blockIdx.y, ch = blockIdx.x, t = threadIdx.x;
    float gw[E_][4];
#pragma unroll
    for (int e = 0; e < E_; e++) {
        float4 v = *(const float4*)(gate_w + e * D_ + t * 4);
        gw[e][0] = v.x; gw[e][1] = v.y; gw[e][2] = v.z; gw[e][3] = v.w;
    }
    float acc[E_];
#pragma unroll
    for (int e = 0; e < E_; e++) acc[e] = 0.0f;

    const float* xb = x + ((size_t)b * S_ + (size_t)ch * 128) * D_ + t * 4;
#pragma unroll 4
    for (int s = 0; s < 128; s++) {
        float4 v = *(const float4*)(xb + (size_t)s * D_);
#pragma unroll
        for (int e = 0; e < E_; e++)
            acc[e] += v.x * gw[e][0] + v.y * gw[e][1] + v.z * gw[e][2] + v.w * gw[e][3];
    }

    __shared__ float red[E_ * 256];
#pragma unroll
    for (int e = 0; e < E_; e++) red[e * 256 + t] = acc[e];
    __syncthreads();
    for (int off = 128; off > 0; off >>= 1) {
        if (t < off) {
#pragma unroll
            for (int e = 0; e < E_; e++) red[e * 256 + t] += red[e * 256 + t + off];
        }
        __syncthreads();
    }
    if (t < E_) g_partial[b][ch][t] = red[t * 256];
}

// ---------------- kernel 2: router (softmax, top-2, renorm, bias vector) ----------------
// grid 32, 128 threads.
__global__ void k_router(const float* __restrict__ up_b) {
    int b = blockIdx.x, t = threadIdx.x;
    __shared__ float sw[2];
    __shared__ int se[2];
    if (t == 0) {
        float lg[E_];
        for (int e = 0; e < E_; e++) {
            float s = 0.0f;
            for (int c = 0; c < 16; c++) s += g_partial[b][c][e];
            lg[e] = s * (1.0f / (float)S_);   // pooled @ gate_w^T
        }
        int i0 = 0;
        for (int e = 1; e < E_; e++) if (lg[e] > lg[i0]) i0 = e;
        int i1 = (i0 == 0) ? 1 : 0;
        for (int e = 0; e < E_; e++) if (e != i0 && lg[e] > lg[i1]) i1 = e;
        float m = lg[i0], Z = 0.0f;
        for (int e = 0; e < E_; e++) Z += expf(lg[e] - m);
        float g0 = expf(lg[i0] - m) / Z;
        float g1 = expf(lg[i1] - m) / Z;
        float dn = g0 + g1 + 1e-8f;
        sw[0] = g0 / dn; sw[1] = g1 / dn; se[0] = i0; se[1] = i1;
        g_eidx[b][0] = i0; g_eidx[b][1] = i1;
        g_ew[b][0] = sw[0]; g_ew[b][1] = sw[1];
    }
    __syncthreads();
    float w0 = sw[0], w1 = sw[1];
    int e0 = se[0], e1 = se[1];
    for (int d = t; d < D_; d += blockDim.x)
        g_bvec[b][d] = w0 * up_b[e0 * D_ + d] + w1 * up_b[e1 * D_ + d];
}

// ---------------- kernel 3: down GEMM + bias + GELU + routing weight ----------------
// grid (16 s-tiles, 32 b), 256 threads (8 warps). Block tile: 128(s) x 128(n = 2 experts x 64).
__global__ void __launch_bounds__(256) k_down(const float* __restrict__ x,
                                              const float* __restrict__ down_w,
                                              const float* __restrict__ down_b) {
    __shared__ unsigned As[128][36];   // stride 36: 36 mod 32 == 4 -> conflict-free frag loads
    __shared__ unsigned Bs[128][36];
    int st = blockIdx.x, b = blockIdx.y, t = threadIdx.x;
    int e0 = g_eidx[b][0], e1 = g_eidx[b][1];
    float w0 = g_ew[b][0], w1 = g_ew[b][1];
    const float* xb = x + ((size_t)b * S_ + (size_t)st * 128) * D_;

    int warp = t >> 5, lane = t & 31;
    int wr = warp >> 1, wc = warp & 1;       // warp tile: rows 32*wr, cols 64*wc
    int g = lane >> 2, tg = lane & 3;

    float acc[2][8][4];
#pragma unroll
    for (int mi = 0; mi < 2; mi++)
#pragma unroll
        for (int ni = 0; ni < 8; ni++)
#pragma unroll
            for (int q = 0; q < 4; q++) acc[mi][ni][q] = 0.0f;

    for (int kk = 0; kk < D_; kk += 32) {
#pragma unroll
        for (int j = 0; j < 4; j++) {
            int idx = t + j * 256, r = idx >> 3, c = (idx & 7) * 4;
            float4 v = *(const float4*)(xb + (size_t)r * D_ + kk + c);
            As[r][c] = f2tf(v.x); As[r][c + 1] = f2tf(v.y);
            As[r][c + 2] = f2tf(v.z); As[r][c + 3] = f2tf(v.w);
        }
#pragma unroll
        for (int j = 0; j < 4; j++) {
            int idx = t + j * 256, n = idx >> 3, c = (idx & 7) * 4;
            int e = (n < 64) ? e0 : e1;
            const float* wp = down_w + ((size_t)e * BN_ + (n & 63)) * D_ + kk + c;
            float4 v = *(const float4*)wp;
            Bs[n][c] = f2tf(v.x); Bs[n][c + 1] = f2tf(v.y);
            Bs[n][c + 2] = f2tf(v.z); Bs[n][c + 3] = f2tf(v.w);
        }
        __syncthreads();
#pragma unroll
        for (int ks = 0; ks < 32; ks += 8) {
            unsigned a[2][4], bf[8][2];
#pragma unroll
            for (int mi = 0; mi < 2; mi++) {
                int r = wr * 32 + mi * 16;
                a[mi][0] = As[r + g][ks + tg];
                a[mi][1] = As[r + g + 8][ks + tg];
                a[mi][2] = As[r + g][ks + tg + 4];
                a[mi][3] = As[r + g + 8][ks + tg + 4];
            }
#pragma unroll
            for (int ni = 0; ni < 8; ni++) {
                int n = wc * 64 + ni * 8;
                bf[ni][0] = Bs[n + g][ks + tg];
                bf[ni][1] = Bs[n + g][ks + tg + 4];
            }
#pragma unroll
            for (int mi = 0; mi < 2; mi++)
#pragma unroll
                for (int ni = 0; ni < 8; ni++)
                    MMA_TF32(acc[mi][ni], a[mi], bf[ni]);
        }
        __syncthreads();
    }

    // epilogue: bias -> exact GELU -> * routing weight -> h[(b,kexp,s,c)]
    int e = wc ? e1 : e0;
    float w = wc ? w1 : w0;
    float* hb = g_h + ((size_t)(b * 2 + wc) * S_ + (size_t)st * 128) * BN_;
#pragma unroll
    for (int mi = 0; mi < 2; mi++) {
#pragma unroll
        for (int ni = 0; ni < 8; ni++) {
            int c = ni * 8 + tg * 2;
            float bd0 = down_b[e * BN_ + c], bd1 = down_b[e * BN_ + c + 1];
            int r0 = wr * 32 + mi * 16 + g;
            float v0 = gelu_exact(acc[mi][ni][0] + bd0) * w;
            float v1 = gelu_exact(acc[mi][ni][1] + bd1) * w;
            float v2 = gelu_exact(acc[mi][ni][2] + bd0) * w;
            float v3 = gelu_exact(acc[mi][ni][3] + bd1) * w;
            *(float2*)(hb + (size_t)r0 * BN_ + c) = make_float2(v0, v1);
            *(float2*)(hb + (size_t)(r0 + 8) * BN_ + c) = make_float2(v2, v3);
        }
    }
}

// ---------------- kernel 4: up GEMM (K=128 concat over 2 experts) + bias vector ----------------
// grid (8 d-chunks, 16 s-tiles, 32 b), 256 threads. Block tile: 128(s) x 128(d).
__global__ void __launch_bounds__(256) k_up(const float* __restrict__ up_w,
                                            float* __restrict__ out) {
    __shared__ unsigned As[128][36];
    __shared__ unsigned Bs[128][36];
    int dc = blockIdx.x, st = blockIdx.y, b = blockIdx.z, t = threadIdx.x;
    int e0 = g_eidx[b][0], e1 = g_eidx[b][1];
    int d0 = dc * 128;

    int warp = t >> 5, lane = t & 31;
    int wr = warp >> 1, wc = warp & 1;
    int g = lane >> 2, tg = lane & 3;

    float acc[2][8][4];
#pragma unroll
    for (int mi = 0; mi < 2; mi++)
#pragma unroll
        for (int ni = 0; ni < 8; ni++)
#pragma unroll
            for (int q = 0; q < 4; q++) acc[mi][ni][q] = 0.0f;

    for (int kk = 0; kk < 128; kk += 32) {
        int kexp = kk >> 6;          // 0 for k<64 (expert 0), 1 for k>=64 (expert 1)
        int cb = kk & 63;
        int e = kexp ? e1 : e0;
        const float* hb = g_h + ((size_t)(b * 2 + kexp) * S_ + (size_t)st * 128) * BN_ + cb;
        const float* wp0 = up_w + (size_t)e * D_ * BN_ + (size_t)d0 * BN_ + cb;
#pragma unroll
        for (int j = 0; j < 4; j++) {
            int idx = t + j * 256, r = idx >> 3, c = (idx & 7) * 4;
            float4 v = *(const float4*)(hb + (size_t)r * BN_ + c);
            As[r][c] = f2tf(v.x); As[r][c + 1] = f2tf(v.y);
            As[r][c + 2] = f2tf(v.z); As[r][c + 3] = f2tf(v.w);
        }
#pragma unroll
        for (int j = 0; j < 4; j++) {
            int idx = t + j * 256, n = idx >> 3, c = (idx & 7) * 4;
            float4 v = *(const float4*)(wp0 + (size_t)n * BN_ + c);
            Bs[n][c] = f2tf(v.x); Bs[n][c + 1] = f2tf(v.y);
            Bs[n][c + 2] = f2tf(v.z); Bs[n][c + 3] = f2tf(v.w);
        }
        __syncthreads();
#pragma unroll
        for (int ks = 0; ks < 32; ks += 8) {
            unsigned a[2][4], bf[8][2];
#pragma unroll
            for (int mi = 0; mi < 2; mi++) {
                int r = wr * 32 + mi * 16;
                a[mi][0] = As[r + g][ks + tg];
                a[mi][1] = As[r + g + 8][ks + tg];
                a[mi][2] = As[r + g][ks + tg + 4];
                a[mi][3] = As[r + g + 8][ks + tg + 4];
            }
#pragma unroll
            for (int ni = 0; ni < 8; ni++) {
                int n = wc * 64 + ni * 8;
                bf[ni][0] = Bs[n + g][ks + tg];
                bf[ni][1] = Bs[n + g][ks + tg + 4];
            }
#pragma unroll
            for (int mi = 0; mi < 2; mi++)
#pragma unroll
                for (int ni = 0; ni < 8; ni++)
                    MMA_TF32(acc[mi][ni], a[mi], bf[ni]);
        }
        __syncthreads();
    }

    float* ob = out + ((size_t)b * S_ + (size_t)st * 128) * D_ + d0;
    const float* bv = g_bvec[b] + d0;
#pragma unroll
    for (int mi = 0; mi < 2; mi++) {
#pragma unroll
        for (int ni = 0; ni < 8; ni++) {
            int n = wc * 64 + ni * 8 + tg * 2;
            int r0 = wr * 32 + mi * 16 + g;
            float bv0 = bv[n], bv1 = bv[n + 1];
            *(float2*)(ob + (size_t)r0 * D_ + n) =
                make_float2(acc[mi][ni][0] + bv0, acc[mi][ni][1] + bv1);
            *(float2*)(ob + (size_t)(r0 + 8) * D_ + n) =
                make_float2(acc[mi][ni][2] + bv0, acc[mi][ni][3] + bv1);
        }
    }
}

// ---------------- launch ----------------
extern "C" void kernel_launch(void* const* d_in, const int* in_sizes, int n_in,
                              void* d_out, int out_size) {
    const float* x      = (const float*)d_in[0];
    const float* gate_w = (const float*)d_in[1];
    const float* down_w = (const float*)d_in[2];
    const float* down_b = (const float*)d_in[3];
    const float* up_w   = (const float*)d_in[4];
    const float* up_b   = (const float*)d_in[5];
    float* out = (float*)d_out;

    k_gate_partial<<<dim3(16, B_), 256>>>(x, gate_w);
    k_router<<<B_, 128>>>(up_b);
    k_down<<<dim3(16, B_), 256>>>(x, down_w, down_b);
    k_up<<<dim3(8, 16, B_), 256>>>(up_w, out);
}

// round 4
// speedup vs baseline: 1.0329x; 1.0329x over previous
#include <cuda_runtime.h>
#include <math.h>

#define B_  32
#define S_  2048
#define D_  1024
#define BN_ 64
#define E_  8

// ---------------- scratch (device globals; no allocation) ----------------
__device__ float g_partial[B_][16][E_];
__device__ int   g_eidx[B_][2];
__device__ float g_ew[B_][2];
__device__ float g_bvec[B_][D_];

// ---------------- helpers ----------------
__device__ __forceinline__ unsigned f2tf(float f) {
    unsigned u; asm("cvt.rna.tf32.f32 %0, %1;" : "=r"(u) : "f"(f)); return u;
}
__device__ __forceinline__ float gelu_exact(float v) {
    return 0.5f * v * (1.0f + erff(v * 0.7071067811865476f));
}

#define MMA_TF32(d, a, bb) asm volatile( \
    "mma.sync.aligned.m16n8k8.row.col.f32.tf32.tf32.f32 " \
    "{%0,%1,%2,%3},{%4,%5,%6,%7},{%8,%9},{%0,%1,%2,%3};" \
    : "+f"(d[0]), "+f"(d[1]), "+f"(d[2]), "+f"(d[3]) \
    : "r"(a[0]), "r"(a[1]), "r"(a[2]), "r"(a[3]), "r"(bb[0]), "r"(bb[1]))

// ---------------- kernel 1: gate logit partials ----------------
__global__ void __launch_bounds__(256) k_gate_partial(const float* __restrict__ x,
                                                      const float* __restrict__ gate_w) {
    int b = blockIdx.y, ch = blockIdx.x, t = threadIdx.x;
    float gw[E_][4];
#pragma unroll
    for (int e = 0; e < E_; e++) {
        float4 v = *(const float4*)(gate_w + e * D_ + t * 4);
        gw[e][0] = v.x; gw[e][1] = v.y; gw[e][2] = v.z; gw[e][3] = v.w;
    }
    float acc[E_];
#pragma unroll
    for (int e = 0; e < E_; e++) acc[e] = 0.0f;

    const float* xb = x + ((size_t)b * S_ + (size_t)ch * 128) * D_ + t * 4;
#pragma unroll 4
    for (int s = 0; s < 128; s++) {
        float4 v = *(const float4*)(xb + (size_t)s * D_);
#pragma unroll
        for (int e = 0; e < E_; e++)
            acc[e] += v.x * gw[e][0] + v.y * gw[e][1] + v.z * gw[e][2] + v.w * gw[e][3];
    }

    __shared__ float red[E_ * 256];
#pragma unroll
    for (int e = 0; e < E_; e++) red[e * 256 + t] = acc[e];
    __syncthreads();
    for (int off = 128; off > 0; off >>= 1) {
        if (t < off) {
#pragma unroll
            for (int e = 0; e < E_; e++) red[e * 256 + t] += red[e * 256 + t + off];
        }
        __syncthreads();
    }
    if (t < E_) g_partial[b][ch][t] = red[t * 256];
}

// ---------------- kernel 2: router ----------------
__global__ void k_router(const float* __restrict__ up_b) {
    int b = blockIdx.x, t = threadIdx.x;
    __shared__ float sw[2];
    __shared__ int se[2];
    if (t == 0) {
        float lg[E_];
        for (int e = 0; e < E_; e++) {
            float s = 0.0f;
            for (int c = 0; c < 16; c++) s += g_partial[b][c][e];
            lg[e] = s * (1.0f / (float)S_);
        }
        int i0 = 0;
        for (int e = 1; e < E_; e++) if (lg[e] > lg[i0]) i0 = e;
        int i1 = (i0 == 0) ? 1 : 0;
        for (int e = 0; e < E_; e++) if (e != i0 && lg[e] > lg[i1]) i1 = e;
        float m = lg[i0], Z = 0.0f;
        for (int e = 0; e < E_; e++) Z += expf(lg[e] - m);
        float g0 = expf(lg[i0] - m) / Z;
        float g1 = expf(lg[i1] - m) / Z;
        float dn = g0 + g1 + 1e-8f;
        sw[0] = g0 / dn; sw[1] = g1 / dn; se[0] = i0; se[1] = i1;
        g_eidx[b][0] = i0; g_eidx[b][1] = i1;
        g_ew[b][0] = sw[0]; g_ew[b][1] = sw[1];
    }
    __syncthreads();
    float w0 = sw[0], w1 = sw[1];
    int e0 = se[0], e1 = se[1];
    for (int d = t; d < D_; d += blockDim.x)
        g_bvec[b][d] = w0 * up_b[e0 * D_ + d] + w1 * up_b[e1 * D_ + d];
}

// ---------------- fused down(+GELU+gate) -> up kernel ----------------
// grid (16 s-tiles, 32 b), 512 threads (16 warps).
// Phase 1: h[128 s][128 n] = GELU(x[128,1024] @ down_w^T + bd) * w  -> SMEM (tf32)
// Phase 2: out[128 s][1024 d] = h @ up_w^T + bvec, looped over 4 d-chunks of 256.
//
// Dynamic smem (words):
//  region0 [0, 18432): phase1 As[2][128][36] + Bs[2][128][36]  (aliased: phase2 B2[2][256][36])
//  region1 [18432, 35328): H[128][132]
#define SMEM_WORDS 35328
#define AS(buf, r, c) sm[(buf) * 4608 + (r) * 36 + (c)]
#define BS(buf, r, c) sm[9216 + (buf) * 4608 + (r) * 36 + (c)]
#define B2(buf, r, c) sm[(buf) * 9216 + (r) * 36 + (c)]
#define HS(r, c)      sm[18432 + (r) * 132 + (c)]

__global__ void __launch_bounds__(512, 1) k_moe_fused(const float* __restrict__ x,
                                                      const float* __restrict__ down_w,
                                                      const float* __restrict__ down_b,
                                                      const float* __restrict__ up_w,
                                                      float* __restrict__ out) {
    extern __shared__ unsigned sm[];
    int st = blockIdx.x, b = blockIdx.y, t = threadIdx.x;
    int e0 = g_eidx[b][0], e1 = g_eidx[b][1];
    float w0 = g_ew[b][0], w1 = g_ew[b][1];
    const float* xb = x + ((size_t)b * S_ + (size_t)st * 128) * D_;

    int warp = t >> 5, lane = t & 31;
    int wr = warp >> 2, wc = warp & 3;
    int g = lane >> 2, tg = lane & 3;

    // ================= Phase 1: down GEMM =================
    {
        float4 pa[2], pb[2];
        float acc[2][4][4];
#pragma unroll
        for (int mi = 0; mi < 2; mi++)
#pragma unroll
            for (int ni = 0; ni < 4; ni++)
#pragma unroll
                for (int q = 0; q < 4; q++) acc[mi][ni][q] = 0.0f;

        auto ldA = [&](int ck) {
#pragma unroll
            for (int j = 0; j < 2; j++) {
                int idx = t + j * 512, r = idx >> 3, c = (idx & 7) * 4;
                pa[j] = *(const float4*)(xb + (size_t)r * D_ + ck * 32 + c);
            }
        };
        auto ldB = [&](int ck) {
#pragma unroll
            for (int j = 0; j < 2; j++) {
                int idx = t + j * 512, n = idx >> 3, c = (idx & 7) * 4;
                int e = (n < 64) ? e0 : e1;
                pb[j] = *(const float4*)(down_w + ((size_t)e * BN_ + (n & 63)) * D_ + ck * 32 + c);
            }
        };
        auto stAB = [&](int buf) {
#pragma unroll
            for (int j = 0; j < 2; j++) {
                int idx = t + j * 512, r = idx >> 3, c = (idx & 7) * 4;
                unsigned* p = &AS(buf, r, c);
                p[0] = f2tf(pa[j].x); p[1] = f2tf(pa[j].y); p[2] = f2tf(pa[j].z); p[3] = f2tf(pa[j].w);
                unsigned* q = &BS(buf, r, c);
                q[0] = f2tf(pb[j].x); q[1] = f2tf(pb[j].y); q[2] = f2tf(pb[j].z); q[3] = f2tf(pb[j].w);
            }
        };

        ldA(0); ldB(0);
        stAB(0);
        __syncthreads();
        ldA(1); ldB(1);

        for (int ck = 0; ck < 32; ck++) {
            int cur = ck & 1;
            if (ck + 1 < 32) stAB(cur ^ 1);
            if (ck + 2 < 32) { ldA(ck + 2); ldB(ck + 2); }
            __syncthreads();
#pragma unroll
            for (int ks = 0; ks < 32; ks += 8) {
                unsigned a[2][4], bf[4][2];
#pragma unroll
                for (int mi = 0; mi < 2; mi++) {
                    int r = wr * 32 + mi * 16;
                    a[mi][0] = AS(cur, r + g, ks + tg);
                    a[mi][1] = AS(cur, r + g + 8, ks + tg);
                    a[mi][2] = AS(cur, r + g, ks + tg + 4);
                    a[mi][3] = AS(cur, r + g + 8, ks + tg + 4);
                }
#pragma unroll
                for (int ni = 0; ni < 4; ni++) {
                    int n = wc * 32 + ni * 8;
                    bf[ni][0] = BS(cur, n + g, ks + tg);
                    bf[ni][1] = BS(cur, n + g, ks + tg + 4);
                }
#pragma unroll
                for (int mi = 0; mi < 2; mi++)
#pragma unroll
                    for (int ni = 0; ni < 4; ni++)
                        MMA_TF32(acc[mi][ni], a[mi], bf[ni]);
            }
            __syncthreads();
        }

        // epilogue: bias -> exact GELU -> *routing weight -> H (tf32)
#pragma unroll
        for (int mi = 0; mi < 2; mi++) {
#pragma unroll
            for (int ni = 0; ni < 4; ni++) {
                int c = wc * 32 + ni * 8 + tg * 2;
                int e = (c < 64) ? e0 : e1;
                float w = (c < 64) ? w0 : w1;
                float bd0 = down_b[e * BN_ + (c & 63)];
                float bd1 = down_b[e * BN_ + ((c + 1) & 63)];
                int r0 = wr * 32 + mi * 16 + g;
                HS(r0, c)     = f2tf(gelu_exact(acc[mi][ni][0] + bd0) * w);
                HS(r0, c + 1) = f2tf(gelu_exact(acc[mi][ni][1] + bd1) * w);
                HS(r0 + 8, c)     = f2tf(gelu_exact(acc[mi][ni][2] + bd0) * w);
                HS(r0 + 8, c + 1) = f2tf(gelu_exact(acc[mi][ni][3] + bd1) * w);
            }
        }
        __syncthreads();
    }

    // ================= Phase 2: up GEMM (K=128 from H) =================
    float* ob = out + ((size_t)b * S_ + (size_t)st * 128) * D_;
    const float* bvp = g_bvec[b];

    for (int dc = 0; dc < 4; dc++) {
        int d0 = dc * 256;
        float4 p2[4];
        float acc[2][8][4];
#pragma unroll
        for (int mi = 0; mi < 2; mi++)
#pragma unroll
            for (int ni = 0; ni < 8; ni++)
#pragma unroll
                for (int q = 0; q < 4; q++) acc[mi][ni][q] = 0.0f;

        auto ldB2 = [&](int ck) {
#pragma unroll
            for (int j = 0; j < 4; j++) {
                int idx = t + j * 512, n = idx >> 3, c = (idx & 7) * 4;
                int k = ck * 32 + c;
                int e = (k < 64) ? e0 : e1;
                p2[j] = *(const float4*)(up_w + ((size_t)e * D_ + d0 + n) * BN_ + (k & 63));
            }
        };
        auto stB2 = [&](int buf) {
#pragma unroll
            for (int j = 0; j < 4; j++) {
                int idx = t + j * 512, n = idx >> 3, c = (idx & 7) * 4;
                unsigned* p = &B2(buf, n, c);
                p[0] = f2tf(p2[j].x); p[1] = f2tf(p2[j].y); p[2] = f2tf(p2[j].z); p[3] = f2tf(p2[j].w);
            }
        };

        ldB2(0);
        stB2(0);
        __syncthreads();
        ldB2(1);

        for (int ck = 0; ck < 4; ck++) {
            int cur = ck & 1;
            if (ck + 1 < 4) stB2(cur ^ 1);
            if (ck + 2 < 4) ldB2(ck + 2);
            __syncthreads();
#pragma unroll
            for (int ks = 0; ks < 32; ks += 8) {
                int ka = ck * 32 + ks;
                unsigned a[2][4], bf[8][2];
#pragma unroll
                for (int mi = 0; mi < 2; mi++) {
                    int r = wr * 32 + mi * 16;
                    a[mi][0] = HS(r + g, ka + tg);
                    a[mi][1] = HS(r + g + 8, ka + tg);
                    a[mi][2] = HS(r + g, ka + tg + 4);
                    a[mi][3] = HS(r + g + 8, ka + tg + 4);
                }
#pragma unroll
                for (int ni = 0; ni < 8; ni++) {
                    int n = wc * 64 + ni * 8;
                    bf[ni][0] = B2(cur, n + g, ks + tg);
                    bf[ni][1] = B2(cur, n + g, ks + tg + 4);
                }
#pragma unroll
                for (int mi = 0; mi < 2; mi++)
#pragma unroll
                    for (int ni = 0; ni < 8; ni++)
                        MMA_TF32(acc[mi][ni], a[mi], bf[ni]);
            }
            __syncthreads();
        }

        // epilogue: + combined up-bias, write out
#pragma unroll
        for (int mi = 0; mi < 2; mi++) {
#pragma unroll
            for (int ni = 0; ni < 8; ni++) {
                int n = wc * 64 + ni * 8 + tg * 2;
                int dcol = d0 + n;
                float bv0 = bvp[dcol], bv1 = bvp[dcol + 1];
                int r0 = wr * 32 + mi * 16 + g;
                *(float2*)(ob + (size_t)r0 * D_ + dcol) =
                    make_float2(acc[mi][ni][0] + bv0, acc[mi][ni][1] + bv1);
                *(float2*)(ob + (size_t)(r0 + 8) * D_ + dcol) =
                    make_float2(acc[mi][ni][2] + bv0, acc[mi][ni][3] + bv1);
            }
        }
    }
}

// ---------------- launch ----------------
extern "C" void kernel_launch(void* const* d_in, const int* in_sizes, int n_in,
                              void* d_out, int out_size) {
    const float* x      = (const float*)d_in[0];
    const float* gate_w = (const float*)d_in[1];
    const float* down_w = (const float*)d_in[2];
    const float* down_b = (const float*)d_in[3];
    const float* up_w   = (const float*)d_in[4];
    const float* up_b   = (const float*)d_in[5];
    float* out = (float*)d_out;

    cudaFuncSetAttribute(k_moe_fused, cudaFuncAttributeMaxDynamicSharedMemorySize,
                         SMEM_WORDS * 4);

    k_gate_partial<<<dim3(16, B_), 256>>>(x, gate_w);
    k_router<<<B_, 128>>>(up_b);
    k_moe_fused<<<dim3(16, B_), 512, SMEM_WORDS * 4>>>(x, down_w, down_b, up_w, out);
}